// round 12
// baseline (speedup 1.0000x reference)
#include <cuda_runtime.h>
#include <cuda_fp16.h>
#include <stdint.h>

// Problem constants
#define HWC   32768
#define W_IMG 256
#define H_IMG 128
#define NPIX  65536

// conv tile constants
#define APITCHB 80                    // bytes per smem row (40 halfs)
#define ABYTES  (3*128*APITCHB)       // 30720
#define BROWS   258
#define BBYTES  (BROWS*APITCHB)       // 20640
#define BUFB    (ABYTES + BBYTES)     // 51360
#define SMEM_CONV (3*BUFB)            // 154080 (3-stage)

// gemm tile constants
#define GA_BYTES (128*APITCHB)
#define GB_BYTES (256*APITCHB)
#define GBUF     (GA_BYTES+GB_BYTES)
#define SMEM_GEMM (3*GBUF)

// ---------------- scratch (16B-aligned) ----------------
__device__ __align__(16) __half g_cat [(size_t)NPIX*1024];  // NHWC cat
__device__ __align__(16) __half g_t1  [(size_t)NPIX*256];
__device__ __align__(16) float  g_q   [(size_t)NPIX*256];
__device__ __align__(16) __half g_ctx [(size_t)NPIX*256];
__device__ __align__(16) __half g_Wq1 [256*512];            // [out][K]
__device__ __align__(16) __half g_Wq2 [256*256];
__device__ __align__(16) __half g_Wout[512*256];
__device__ __align__(16) __half g_Wre [9u*512*1024];        // [r][o][ci]
__device__ __align__(16) float  g_bq1[256];
__device__ __align__(16) float  g_bq2[256];
__device__ __align__(16) float  g_bout[512];
__device__ __align__(16) float  g_bbot[512];
__device__ __align__(16) float  g_tk1[2*256*19];
__device__ __align__(16) float  g_kf[2*256*19];
__device__ __align__(16) float  g_vf[2*256*19];

// ---------------- helpers ----------------
__device__ __forceinline__ void mma16816(float c[4],
    uint32_t a0, uint32_t a1, uint32_t a2, uint32_t a3,
    uint32_t b0, uint32_t b1)
{
    asm volatile(
        "mma.sync.aligned.m16n8k16.row.col.f32.f16.f16.f32 "
        "{%0,%1,%2,%3}, {%4,%5,%6,%7}, {%8,%9}, {%0,%1,%2,%3};\n"
        : "+f"(c[0]), "+f"(c[1]), "+f"(c[2]), "+f"(c[3])
        : "r"(a0), "r"(a1), "r"(a2), "r"(a3), "r"(b0), "r"(b1));
}

#define LDSM4(R0,R1,R2,R3,ADDR) \
    asm volatile("ldmatrix.sync.aligned.m8n8.x4.shared.b16 {%0,%1,%2,%3}, [%4];" \
        : "=r"(R0),"=r"(R1),"=r"(R2),"=r"(R3) : "r"(ADDR))

#define CP16(DST,SRC) \
    asm volatile("cp.async.cg.shared.global [%0], [%1], 16;\n" :: "r"(DST), "l"(SRC))

template <typename T> struct St;
template <> struct St<__half> {
    static __device__ __forceinline__ void s(__half* p, float a, float b) {
        *reinterpret_cast<__half2*>(p) = __floats2half2_rn(a, b);
    }
};
template <> struct St<float> {
    static __device__ __forceinline__ void s(float* p, float a, float b) {
        *reinterpret_cast<float2*>(p) = make_float2(a, b);
    }
};

// ---------------- prep kernels ----------------
__global__ __launch_bounds__(256) void x_to_cat(
    const float* __restrict__ x, __half* __restrict__ cat)
{
    __shared__ float t[64][65];
    const int tid = threadIdx.x;
    const int px0 = blockIdx.x * 64;
    const int ch0 = blockIdx.y * 64;
    const int b   = blockIdx.z;
    const int r   = tid >> 3, c8 = (tid & 7) * 8;
#pragma unroll
    for (int i = 0; i < 2; i++) {
        int row = r + i * 32;
        const float* src = x + ((size_t)(b * 512 + ch0 + row)) * HWC + px0 + c8;
        float4 v0 = *reinterpret_cast<const float4*>(src);
        float4 v1 = *reinterpret_cast<const float4*>(src + 4);
        t[row][c8 + 0] = v0.x; t[row][c8 + 1] = v0.y;
        t[row][c8 + 2] = v0.z; t[row][c8 + 3] = v0.w;
        t[row][c8 + 4] = v1.x; t[row][c8 + 5] = v1.y;
        t[row][c8 + 6] = v1.z; t[row][c8 + 7] = v1.w;
    }
    __syncthreads();
#pragma unroll
    for (int i = 0; i < 2; i++) {
        int row = r + i * 32;
        __half v[8];
#pragma unroll
        for (int j = 0; j < 8; j++) v[j] = __float2half(t[c8 + j][row]);
        *reinterpret_cast<uint4*>(
            &cat[(((size_t)b * HWC + px0 + row) << 10) + 512 + ch0 + c8]) =
            *reinterpret_cast<uint4*>(v);
    }
}

__global__ void fold_w_kernel(const float* __restrict__ w, const float* __restrict__ bn,
                              __half* __restrict__ Wh, float* __restrict__ bias,
                              int M, int K) {
    int i = blockIdx.x * blockDim.x + threadIdx.x;
    if (i < M) {
        float s = bn[i] * rsqrtf(bn[3 * M + i] + 1e-5f);
        bias[i] = bn[M + i] - bn[2 * M + i] * s;
    }
    if (i < M * K) {
        int m = i / K;
        float s = bn[m] * rsqrtf(bn[3 * M + m] + 1e-5f);
        Wh[i] = __float2half(w[i] * s);
    }
}

__global__ void fold_wbot_kernel(const float* __restrict__ w, const float* __restrict__ bn,
                                 __half* __restrict__ Wre, float* __restrict__ bias) {
    int i = blockIdx.x * blockDim.x + threadIdx.x;
    if (i < 512) {
        float s = bn[i] * rsqrtf(bn[3 * 512 + i] + 1e-5f);
        bias[i] = bn[512 + i] - bn[2 * 512 + i] * s;
    }
    if (i < 9 * 1024 * 512) {
        int ci = i & 1023;
        int o  = (i >> 10) & 511;
        int r  = i >> 19;
        float s = bn[o] * rsqrtf(bn[3 * 512 + o] + 1e-5f);
        Wre[i] = __float2half(w[((size_t)o * 1024 + ci) * 9 + r] * s);
    }
}

__global__ void kv_stage_kernel(const float* __restrict__ W, const float* __restrict__ bn,
                                const float* __restrict__ in, float* __restrict__ out,
                                int M, int K) {
    int i = blockIdx.x * blockDim.x + threadIdx.x;
    if (i >= 2 * M * 19) return;
    int j = i % 19;
    int m = (i / 19) % M;
    int b = i / (19 * M);
    const float* ib = in + (size_t)b * K * 19;
    float acc = 0.f;
    for (int c = 0; c < K; c++) acc += W[(size_t)m * K + c] * ib[c * 19 + j];
    float s = bn[m] * rsqrtf(bn[3 * M + m] + 1e-5f);
    out[i] = fmaxf(acc * s + (bn[M + m] - bn[2 * M + m] * s), 0.f);
}

// ---------------- NHWC GEMM (1x1 convs, proven R4 version) ----------------
__device__ __forceinline__ void gemm_fill(
    uint32_t sbase, int bufo, int s, int tid, int pix0, int out0, int Pa, int K,
    const __half* __restrict__ A, const __half* __restrict__ W)
{
    const int kc = s << 5;
    {
        const int row = tid >> 2, part = tid & 3;
        CP16(sbase + bufo + row * APITCHB + part * 16,
             A + (size_t)(pix0 + row) * Pa + kc + part * 8);
    }
#pragma unroll
    for (int i = 0; i < 2; i++) {
        const int j = tid + i * 512;
        const int row = j >> 2, part = j & 3;
        CP16(sbase + bufo + GA_BYTES + row * APITCHB + part * 16,
             W + (size_t)(out0 + row) * K + kc + part * 8);
    }
}

template <typename OutT>
__global__ __launch_bounds__(512, 1) void gemm_nhwc(
    const __half* __restrict__ A, int Pa,
    const __half* __restrict__ W,
    const float*  __restrict__ bias,
    OutT*         __restrict__ Out,
    int Po, int K)
{
    extern __shared__ char smemg[];
    const uint32_t sbase = (uint32_t)__cvta_generic_to_shared(smemg);
    const int tid  = threadIdx.x;
    const int warp = tid >> 5, lane = tid & 31;
    const int wm   = (warp >> 2) * 32;
    const int wn   = (warp & 3) * 64;
    const int pix0 = blockIdx.x * 128;
    const int out0 = blockIdx.y * 256;
    const int steps = K >> 5;

    float c[2][8][4];
#pragma unroll
    for (int i = 0; i < 2; i++)
#pragma unroll
        for (int j = 0; j < 8; j++)
#pragma unroll
            for (int r = 0; r < 4; r++) c[i][j][r] = 0.f;

    gemm_fill(sbase, 0, 0, tid, pix0, out0, Pa, K, A, W);
    asm volatile("cp.async.commit_group;\n");
    gemm_fill(sbase, GBUF, 1, tid, pix0, out0, Pa, K, A, W);
    asm volatile("cp.async.commit_group;\n");

    for (int s = 0; s < steps; s++) {
        if (s < steps - 1) asm volatile("cp.async.wait_group 1;\n");
        else               asm volatile("cp.async.wait_group 0;\n");
        __syncthreads();

        const uint32_t aB = sbase + (s % 3) * GBUF;
        const uint32_t bB = aB + GA_BYTES;
        const uint32_t aRow = aB + (wm + (lane & 15)) * APITCHB + (lane >> 4) * 16;
#pragma unroll
        for (int ks = 0; ks < 2; ks++) {
            const int kb2 = ks * 32;
            uint32_t a0[4], a1[4];
            LDSM4(a0[0], a0[1], a0[2], a0[3], aRow + kb2);
            LDSM4(a1[0], a1[1], a1[2], a1[3], aRow + 16 * APITCHB + kb2);
#pragma unroll
            for (int nj = 0; nj < 4; nj++) {
                const int row = wn + nj * 16 + (lane & 7) + ((lane >> 4) & 1) * 8;
                const uint32_t addr = bB + row * APITCHB + kb2 + ((lane >> 3) & 1) * 16;
                uint32_t b0, b1, b2, b3;
                LDSM4(b0, b1, b2, b3, addr);
                mma16816(c[0][nj * 2],     a0[0], a0[1], a0[2], a0[3], b0, b1);
                mma16816(c[0][nj * 2 + 1], a0[0], a0[1], a0[2], a0[3], b2, b3);
                mma16816(c[1][nj * 2],     a1[0], a1[1], a1[2], a1[3], b0, b1);
                mma16816(c[1][nj * 2 + 1], a1[0], a1[1], a1[2], a1[3], b2, b3);
            }
        }
        if (s + 2 < steps) {
            gemm_fill(sbase, ((s + 2) % 3) * GBUF, s + 2, tid, pix0, out0, Pa, K, A, W);
            asm volatile("cp.async.commit_group;\n");
        }
    }

    const int qid = lane >> 2, rid = lane & 3;
#pragma unroll
    for (int mi = 0; mi < 2; mi++) {
        const int pr = pix0 + wm + mi * 16 + qid;
#pragma unroll
        for (int ni = 0; ni < 8; ni++) {
            const int o = out0 + wn + ni * 8 + rid * 2;
            const float2 bb = *reinterpret_cast<const float2*>(bias + o);
            St<OutT>::s(Out + (size_t)pr * Po + o,
                        fmaxf(c[mi][ni][0] + bb.x, 0.f), fmaxf(c[mi][ni][1] + bb.y, 0.f));
            St<OutT>::s(Out + (size_t)(pr + 8) * Po + o,
                        fmaxf(c[mi][ni][2] + bb.x, 0.f), fmaxf(c[mi][ni][3] + bb.y, 0.f));
        }
    }
}

// ---------------- attention ----------------
__global__ __launch_bounds__(256) void attn_nhwc(
    const float* __restrict__ q,
    const float* __restrict__ kf,
    const float* __restrict__ vf,
    __half* __restrict__ ctx)
{
    __shared__ float ks[256 * 19];
    __shared__ float vs[256 * 19];
    const int tid = threadIdx.x;
    const int p0  = blockIdx.x * 8;
    const int b   = p0 / HWC;
    for (int i = tid; i < 256 * 19; i += 256) {
        ks[i] = kf[b * 256 * 19 + i];
        vs[i] = vf[b * 256 * 19 + i];
    }
    __syncthreads();
    const int warp = tid >> 5, lane = tid & 31;
    const int pix = p0 + warp;
    const float* qp = q + (size_t)pix * 256;

    float qv[8];
#pragma unroll
    for (int i = 0; i < 8; i++) qv[i] = qp[lane + 32 * i];

    float sim[19];
#pragma unroll
    for (int j = 0; j < 19; j++) {
        float s = 0.f;
#pragma unroll
        for (int i = 0; i < 8; i++) s += qv[i] * ks[(lane + 32 * i) * 19 + j];
#pragma unroll
        for (int o = 16; o > 0; o >>= 1) s += __shfl_xor_sync(0xffffffffu, s, o);
        sim[j] = s * 0.0625f;
    }
    float mx = sim[0];
#pragma unroll
    for (int j = 1; j < 19; j++) mx = fmaxf(mx, sim[j]);
    float den = 0.f;
#pragma unroll
    for (int j = 0; j < 19; j++) { sim[j] = __expf(sim[j] - mx); den += sim[j]; }
    float inv = 1.f / den;

    __half* cp = ctx + (size_t)pix * 256;
#pragma unroll
    for (int i = 0; i < 8; i++) {
        int c = lane + 32 * i;
        float acc = 0.f;
#pragma unroll
        for (int j = 0; j < 19; j++) acc += sim[j] * vs[c * 19 + j];
        cp[c] = __float2half(acc * inv);
    }
}

// ---------------- conv3x3: 256 threads, warp tile 64x64 (HMMA-bound config) ----------------
__device__ __forceinline__ void conv_stage(
    uint32_t sbase, char* smemc, int bufo, int s,
    int tid, int b, int y0, int m0,
    const __half* __restrict__ Wre2, const __half* __restrict__ nhwc)
{
    const int dy = s >> 5;
    const int kc = (s & 31) << 5;
    // A: 3 taps x 128 rows x 4 parts = 1536 cp16 over 256 threads
#pragma unroll
    for (int i = 0; i < 6; i++) {
        const int idx = tid + i * 256;
        const int t = idx >> 9;
        const int m = (idx >> 2) & 127;
        const int part = idx & 3;
        const __half* g = Wre2 + (((size_t)((dy * 3 + t) * 512 + m0 + m)) << 10)
                          + kc + part * 8;
        CP16(sbase + bufo + (t * 128 + m) * APITCHB + part * 16, g);
    }
    // B: 258 rows x 4 parts = 1032 cp16
    {
        const int yy = y0 + dy - 1;
        const bool yok = (unsigned)yy < (unsigned)H_IMG;
        const __half* rowbase = nhwc + (((size_t)(b * H_IMG + yy) * W_IMG) << 10) + kc;
#pragma unroll
        for (int i = 0; i < 5; i++) {
            int j = tid + i * 256;
            if (j < BROWS * 4) {
                int n = j >> 2, p = j & 3;
                uint32_t doff = (uint32_t)bufo + ABYTES + n * APITCHB + p * 16;
                int xx = n - 1;
                if (yok && (unsigned)xx < (unsigned)W_IMG) {
                    CP16(sbase + doff, rowbase + ((size_t)xx << 10) + p * 8);
                } else {
                    *reinterpret_cast<uint4*>(smemc + doff) = make_uint4(0, 0, 0, 0);
                }
            }
        }
    }
}

__global__ __launch_bounds__(256, 1) void conv3_tc(
    const __half* __restrict__ Wre2,
    const __half* __restrict__ nhwc,
    const float*  __restrict__ bias,
    float*        __restrict__ Out)
{
    extern __shared__ char smemc[];
    const uint32_t sbase = (uint32_t)__cvta_generic_to_shared(smemc);
    const int tid  = threadIdx.x;
    const int warp = tid >> 5, lane = tid & 31;
    const int wm   = (warp >> 2) * 64;    // 2 m-warps x 64 rows
    const int wn   = (warp & 3) * 64;     // 4 n-warps x 64 cols
    const int m0   = blockIdx.y * 128;
    const int b    = blockIdx.x >> 7;
    const int y0   = blockIdx.x & 127;

    float c[4][8][4];
#pragma unroll
    for (int i = 0; i < 4; i++)
#pragma unroll
        for (int j = 0; j < 8; j++)
#pragma unroll
            for (int r = 0; r < 4; r++) c[i][j][r] = 0.f;

    conv_stage(sbase, smemc, 0, 0, tid, b, y0, m0, Wre2, nhwc);
    asm volatile("cp.async.commit_group;\n");
    conv_stage(sbase, smemc, BUFB, 1, tid, b, y0, m0, Wre2, nhwc);
    asm volatile("cp.async.commit_group;\n");

    for (int s = 0; s < 96; s++) {
        if (s < 95) asm volatile("cp.async.wait_group 1;\n");
        else        asm volatile("cp.async.wait_group 0;\n");
        __syncthreads();

        const uint32_t aB = sbase + (s % 3) * BUFB;
        const uint32_t bB = aB + ABYTES;
#pragma unroll
        for (int dx = 0; dx < 3; dx++) {
            const uint32_t aRow = aB + (dx * 128 + wm + (lane & 15)) * APITCHB
                                  + (lane >> 4) * 16;
#pragma unroll
            for (int ks = 0; ks < 2; ks++) {
                const int kb2 = ks * 32;
                uint32_t a[4][4];
#pragma unroll
                for (int mf = 0; mf < 4; mf++)
                    LDSM4(a[mf][0], a[mf][1], a[mf][2], a[mf][3],
                          aRow + mf * 16 * APITCHB + kb2);
#pragma unroll
                for (int nj = 0; nj < 4; nj++) {
                    const int row = wn + nj * 16 + dx + (lane & 7) + ((lane >> 4) & 1) * 8;
                    const uint32_t addr = bB + row * APITCHB + kb2 + ((lane >> 3) & 1) * 16;
                    uint32_t b0, b1, b2, b3;
                    LDSM4(b0, b1, b2, b3, addr);
#pragma unroll
                    for (int mf = 0; mf < 4; mf++) {
                        mma16816(c[mf][nj * 2],     a[mf][0], a[mf][1], a[mf][2], a[mf][3], b0, b1);
                        mma16816(c[mf][nj * 2 + 1], a[mf][0], a[mf][1], a[mf][2], a[mf][3], b2, b3);
                    }
                }
            }
        }
        if (s + 2 < 96) {
            conv_stage(sbase, smemc, ((s + 2) % 3) * BUFB, s + 2, tid, b, y0, m0, Wre2, nhwc);
            asm volatile("cp.async.commit_group;\n");
        }
    }

    const int qid = lane >> 2, rid = lane & 3;
    float* outB = Out + ((size_t)b * 512) * HWC + (size_t)y0 * W_IMG;
#pragma unroll
    for (int mf = 0; mf < 4; mf++) {
        const int mr = wm + mf * 16 + qid;
        const float bs0 = bias[m0 + mr], bs1 = bias[m0 + mr + 8];
#pragma unroll
        for (int ni = 0; ni < 8; ni++) {
            const int px = wn + ni * 8 + rid * 2;
            *reinterpret_cast<float2*>(outB + (size_t)(m0 + mr) * HWC + px) =
                make_float2(fmaxf(c[mf][ni][0] + bs0, 0.f),
                            fmaxf(c[mf][ni][1] + bs0, 0.f));
            *reinterpret_cast<float2*>(outB + (size_t)(m0 + mr + 8) * HWC + px) =
                make_float2(fmaxf(c[mf][ni][2] + bs1, 0.f),
                            fmaxf(c[mf][ni][3] + bs1, 0.f));
        }
    }
}

// ---------------- launcher ----------------
extern "C" void kernel_launch(void* const* d_in, const int* in_sizes, int n_in,
                              void* d_out, int out_size)
{
    const float *x, *proxy, *wq1, *wq2, *wk1, *wk2, *wv, *wout, *wbot;
    const float *bnq1, *bnq2, *bnk1, *bnk2, *bnv, *bnout, *bnbot;

    if (n_in >= 16 && in_sizes[3] == 1024) {
        x     = (const float*)d_in[0];  proxy = (const float*)d_in[1];
        wq1   = (const float*)d_in[2];  bnq1  = (const float*)d_in[3];
        wq2   = (const float*)d_in[4];  bnq2  = (const float*)d_in[5];
        wk1   = (const float*)d_in[6];  bnk1  = (const float*)d_in[7];
        wk2   = (const float*)d_in[8];  bnk2  = (const float*)d_in[9];
        wv    = (const float*)d_in[10]; bnv   = (const float*)d_in[11];
        wout  = (const float*)d_in[12]; bnout = (const float*)d_in[13];
        wbot  = (const float*)d_in[14]; bnbot = (const float*)d_in[15];
    } else {
        x     = (const float*)d_in[0];  proxy = (const float*)d_in[1];
        wq1   = (const float*)d_in[2];  wq2   = (const float*)d_in[3];
        wk1   = (const float*)d_in[4];  wk2   = (const float*)d_in[5];
        wv    = (const float*)d_in[6];  wout  = (const float*)d_in[7];
        wbot  = (const float*)d_in[8];
        bnq1  = (const float*)d_in[9];  bnq2  = (const float*)d_in[10];
        bnk1  = (const float*)d_in[11]; bnk2  = (const float*)d_in[12];
        bnv   = (const float*)d_in[13]; bnout = (const float*)d_in[14];
        bnbot = (const float*)d_in[15];
    }

    __half *cat, *t1, *ctx, *Wq1h, *Wq2h, *Wouth, *Wre;
    float *q, *bq1, *bq2, *bout, *bbot, *tk1, *kf, *vf;
    cudaGetSymbolAddress((void**)&cat,   g_cat);
    cudaGetSymbolAddress((void**)&t1,    g_t1);
    cudaGetSymbolAddress((void**)&q,     g_q);
    cudaGetSymbolAddress((void**)&ctx,   g_ctx);
    cudaGetSymbolAddress((void**)&Wq1h,  g_Wq1);
    cudaGetSymbolAddress((void**)&Wq2h,  g_Wq2);
    cudaGetSymbolAddress((void**)&Wouth, g_Wout);
    cudaGetSymbolAddress((void**)&Wre,   g_Wre);
    cudaGetSymbolAddress((void**)&bq1,   g_bq1);
    cudaGetSymbolAddress((void**)&bq2,   g_bq2);
    cudaGetSymbolAddress((void**)&bout,  g_bout);
    cudaGetSymbolAddress((void**)&bbot,  g_bbot);
    cudaGetSymbolAddress((void**)&tk1,   g_tk1);
    cudaGetSymbolAddress((void**)&kf,    g_kf);
    cudaGetSymbolAddress((void**)&vf,    g_vf);

    cudaFuncSetAttribute(conv3_tc, cudaFuncAttributeMaxDynamicSharedMemorySize, SMEM_CONV);
    cudaFuncSetAttribute(gemm_nhwc<__half>, cudaFuncAttributeMaxDynamicSharedMemorySize, SMEM_GEMM);
    cudaFuncSetAttribute(gemm_nhwc<float>,  cudaFuncAttributeMaxDynamicSharedMemorySize, SMEM_GEMM);

    // --- prep ---
    x_to_cat<<<dim3(HWC / 64, 8, 2), 256>>>(x, cat);
    fold_w_kernel<<<(256 * 512 + 255) / 256, 256>>>(wq1, bnq1, Wq1h, bq1, 256, 512);
    fold_w_kernel<<<(256 * 256 + 255) / 256, 256>>>(wq2, bnq2, Wq2h, bq2, 256, 256);
    fold_w_kernel<<<(512 * 256 + 255) / 256, 256>>>(wout, bnout, Wouth, bout, 512, 256);
    fold_wbot_kernel<<<(9 * 1024 * 512 + 255) / 256, 256>>>(wbot, bnbot, Wre, bbot);

    // --- tiny k/v path ---
    kv_stage_kernel<<<(2 * 256 * 19 + 255) / 256, 256>>>(wk1, bnk1, proxy, tk1, 256, 512);
    kv_stage_kernel<<<(2 * 256 * 19 + 255) / 256, 256>>>(wv,  bnv,  proxy, vf,  256, 512);
    kv_stage_kernel<<<(2 * 256 * 19 + 255) / 256, 256>>>(wk2, bnk2, tk1, kf, 256, 256);

    // --- q path ---
    gemm_nhwc<__half><<<dim3(NPIX / 128, 1), 512, SMEM_GEMM>>>(
        cat + 512, 1024, Wq1h, bq1, t1, 256, 512);
    gemm_nhwc<float><<<dim3(NPIX / 128, 1), 512, SMEM_GEMM>>>(
        t1, 256, Wq2h, bq2, q, 256, 256);

    // --- attention ---
    attn_nhwc<<<NPIX / 8, 256>>>(q, kf, vf, ctx);

    // --- wout GEMM -> cat[pix][0:512] ---
    gemm_nhwc<__half><<<dim3(NPIX / 128, 2), 512, SMEM_GEMM>>>(
        ctx, 256, Wouth, bout, cat, 1024, 256);

    // --- bottleneck conv3x3 ---
    conv3_tc<<<dim3(2 * H_IMG, 4), 256, SMEM_CONV>>>(Wre, cat, bbot, (float*)d_out);
}

// round 14
// speedup vs baseline: 1.0500x; 1.0500x over previous
#include <cuda_runtime.h>
#include <cuda_fp16.h>
#include <stdint.h>

// Problem constants
#define HWC   32768
#define W_IMG 256
#define H_IMG 128
#define NPIX  65536

// conv tile constants
#define APITCHB 80                    // bytes per smem row (40 halfs)
#define ABYTES  (3*128*APITCHB)       // 30720
#define BROWS   258
#define BBYTES  (BROWS*APITCHB)       // 20640
#define BUFB    (ABYTES + BBYTES)     // 51360
#define SMEM_CONV (3*BUFB)            // 154080 (3-stage)

// gemm tile constants
#define GA_BYTES (128*APITCHB)
#define GB_BYTES (256*APITCHB)
#define GBUF     (GA_BYTES+GB_BYTES)
#define SMEM_GEMM (3*GBUF)            // 92160
#define SMEM_FUSED (SMEM_GEMM + 2*256*19*4)   // 131072

// ---------------- scratch (16B-aligned) ----------------
__device__ __align__(16) __half g_cat [(size_t)NPIX*1024];  // NHWC cat
__device__ __align__(16) __half g_t1  [(size_t)NPIX*256];
__device__ __align__(16) __half g_ctx [(size_t)NPIX*256];
__device__ __align__(16) __half g_Wq1 [256*512];            // [out][K]
__device__ __align__(16) __half g_Wq2 [256*256];
__device__ __align__(16) __half g_Wout[512*256];
__device__ __align__(16) __half g_Wre [9u*512*1024];        // [r][o][ci]
__device__ __align__(16) float  g_bq1[256];
__device__ __align__(16) float  g_bq2[256];
__device__ __align__(16) float  g_bout[512];
__device__ __align__(16) float  g_bbot[512];
__device__ __align__(16) float  g_tk1[2*256*19];
__device__ __align__(16) float  g_kf[2*256*19];
__device__ __align__(16) float  g_vf[2*256*19];

// ---------------- helpers ----------------
__device__ __forceinline__ void mma16816(float c[4],
    uint32_t a0, uint32_t a1, uint32_t a2, uint32_t a3,
    uint32_t b0, uint32_t b1)
{
    asm volatile(
        "mma.sync.aligned.m16n8k16.row.col.f32.f16.f16.f32 "
        "{%0,%1,%2,%3}, {%4,%5,%6,%7}, {%8,%9}, {%0,%1,%2,%3};\n"
        : "+f"(c[0]), "+f"(c[1]), "+f"(c[2]), "+f"(c[3])
        : "r"(a0), "r"(a1), "r"(a2), "r"(a3), "r"(b0), "r"(b1));
}

#define LDSM4(R0,R1,R2,R3,ADDR) \
    asm volatile("ldmatrix.sync.aligned.m8n8.x4.shared.b16 {%0,%1,%2,%3}, [%4];" \
        : "=r"(R0),"=r"(R1),"=r"(R2),"=r"(R3) : "r"(ADDR))

#define CP16(DST,SRC) \
    asm volatile("cp.async.cg.shared.global [%0], [%1], 16;\n" :: "r"(DST), "l"(SRC))

template <typename T> struct St;
template <> struct St<__half> {
    static __device__ __forceinline__ void s(__half* p, float a, float b) {
        *reinterpret_cast<__half2*>(p) = __floats2half2_rn(a, b);
    }
};
template <> struct St<float> {
    static __device__ __forceinline__ void s(float* p, float a, float b) {
        *reinterpret_cast<float2*>(p) = make_float2(a, b);
    }
};

// ---------------- prep kernels ----------------
__global__ __launch_bounds__(256) void x_to_cat(
    const float* __restrict__ x, __half* __restrict__ cat)
{
    __shared__ float t[64][65];
    const int tid = threadIdx.x;
    const int px0 = blockIdx.x * 64;
    const int ch0 = blockIdx.y * 64;
    const int b   = blockIdx.z;
    const int r   = tid >> 3, c8 = (tid & 7) * 8;
#pragma unroll
    for (int i = 0; i < 2; i++) {
        int row = r + i * 32;
        const float* src = x + ((size_t)(b * 512 + ch0 + row)) * HWC + px0 + c8;
        float4 v0 = *reinterpret_cast<const float4*>(src);
        float4 v1 = *reinterpret_cast<const float4*>(src + 4);
        t[row][c8 + 0] = v0.x; t[row][c8 + 1] = v0.y;
        t[row][c8 + 2] = v0.z; t[row][c8 + 3] = v0.w;
        t[row][c8 + 4] = v1.x; t[row][c8 + 5] = v1.y;
        t[row][c8 + 6] = v1.z; t[row][c8 + 7] = v1.w;
    }
    __syncthreads();
#pragma unroll
    for (int i = 0; i < 2; i++) {
        int row = r + i * 32;
        __half v[8];
#pragma unroll
        for (int j = 0; j < 8; j++) v[j] = __float2half(t[c8 + j][row]);
        *reinterpret_cast<uint4*>(
            &cat[(((size_t)b * HWC + px0 + row) << 10) + 512 + ch0 + c8]) =
            *reinterpret_cast<uint4*>(v);
    }
}

__global__ void fold_w_kernel(const float* __restrict__ w, const float* __restrict__ bn,
                              __half* __restrict__ Wh, float* __restrict__ bias,
                              int M, int K) {
    int i = blockIdx.x * blockDim.x + threadIdx.x;
    if (i < M) {
        float s = bn[i] * rsqrtf(bn[3 * M + i] + 1e-5f);
        bias[i] = bn[M + i] - bn[2 * M + i] * s;
    }
    if (i < M * K) {
        int m = i / K;
        float s = bn[m] * rsqrtf(bn[3 * M + m] + 1e-5f);
        Wh[i] = __float2half(w[i] * s);
    }
}

__global__ void fold_wbot_kernel(const float* __restrict__ w, const float* __restrict__ bn,
                                 __half* __restrict__ Wre, float* __restrict__ bias) {
    int i = blockIdx.x * blockDim.x + threadIdx.x;
    if (i < 512) {
        float s = bn[i] * rsqrtf(bn[3 * 512 + i] + 1e-5f);
        bias[i] = bn[512 + i] - bn[2 * 512 + i] * s;
    }
    if (i < 9 * 1024 * 512) {
        int ci = i & 1023;
        int o  = (i >> 10) & 511;
        int r  = i >> 19;
        float s = bn[o] * rsqrtf(bn[3 * 512 + o] + 1e-5f);
        Wre[i] = __float2half(w[((size_t)o * 1024 + ci) * 9 + r] * s);
    }
}

__global__ void kv_stage_kernel(const float* __restrict__ W, const float* __restrict__ bn,
                                const float* __restrict__ in, float* __restrict__ out,
                                int M, int K) {
    int i = blockIdx.x * blockDim.x + threadIdx.x;
    if (i >= 2 * M * 19) return;
    int j = i % 19;
    int m = (i / 19) % M;
    int b = i / (19 * M);
    const float* ib = in + (size_t)b * K * 19;
    float acc = 0.f;
    for (int c = 0; c < K; c++) acc += W[(size_t)m * K + c] * ib[c * 19 + j];
    float s = bn[m] * rsqrtf(bn[3 * M + m] + 1e-5f);
    out[i] = fmaxf(acc * s + (bn[M + m] - bn[2 * M + m] * s), 0.f);
}

// ---------------- NHWC GEMM (1x1 convs) ----------------
__device__ __forceinline__ void gemm_fill(
    uint32_t sbase, int bufo, int s, int tid, int pix0, int out0, int Pa, int K,
    const __half* __restrict__ A, const __half* __restrict__ W)
{
    const int kc = s << 5;
    {
        const int row = tid >> 2, part = tid & 3;
        CP16(sbase + bufo + row * APITCHB + part * 16,
             A + (size_t)(pix0 + row) * Pa + kc + part * 8);
    }
#pragma unroll
    for (int i = 0; i < 2; i++) {
        const int j = tid + i * 512;
        const int row = j >> 2, part = j & 3;
        CP16(sbase + bufo + GA_BYTES + row * APITCHB + part * 16,
             W + (size_t)(out0 + row) * K + kc + part * 8);
    }
}

template <typename OutT>
__global__ __launch_bounds__(512, 1) void gemm_nhwc(
    const __half* __restrict__ A, int Pa,
    const __half* __restrict__ W,
    const float*  __restrict__ bias,
    OutT*         __restrict__ Out,
    int Po, int K)
{
    extern __shared__ char smemg[];
    const uint32_t sbase = (uint32_t)__cvta_generic_to_shared(smemg);
    const int tid  = threadIdx.x;
    const int warp = tid >> 5, lane = tid & 31;
    const int wm   = (warp >> 2) * 32;
    const int wn   = (warp & 3) * 64;
    const int pix0 = blockIdx.x * 128;
    const int out0 = blockIdx.y * 256;
    const int steps = K >> 5;

    float c[2][8][4];
#pragma unroll
    for (int i = 0; i < 2; i++)
#pragma unroll
        for (int j = 0; j < 8; j++)
#pragma unroll
            for (int r = 0; r < 4; r++) c[i][j][r] = 0.f;

    gemm_fill(sbase, 0, 0, tid, pix0, out0, Pa, K, A, W);
    asm volatile("cp.async.commit_group;\n");
    gemm_fill(sbase, GBUF, 1, tid, pix0, out0, Pa, K, A, W);
    asm volatile("cp.async.commit_group;\n");

    for (int s = 0; s < steps; s++) {
        if (s < steps - 1) asm volatile("cp.async.wait_group 1;\n");
        else               asm volatile("cp.async.wait_group 0;\n");
        __syncthreads();

        const uint32_t aB = sbase + (s % 3) * GBUF;
        const uint32_t bB = aB + GA_BYTES;
        const uint32_t aRow = aB + (wm + (lane & 15)) * APITCHB + (lane >> 4) * 16;
#pragma unroll
        for (int ks = 0; ks < 2; ks++) {
            const int kb2 = ks * 32;
            uint32_t a0[4], a1[4];
            LDSM4(a0[0], a0[1], a0[2], a0[3], aRow + kb2);
            LDSM4(a1[0], a1[1], a1[2], a1[3], aRow + 16 * APITCHB + kb2);
#pragma unroll
            for (int nj = 0; nj < 4; nj++) {
                const int row = wn + nj * 16 + (lane & 7) + ((lane >> 4) & 1) * 8;
                const uint32_t addr = bB + row * APITCHB + kb2 + ((lane >> 3) & 1) * 16;
                uint32_t b0, b1, b2, b3;
                LDSM4(b0, b1, b2, b3, addr);
                mma16816(c[0][nj * 2],     a0[0], a0[1], a0[2], a0[3], b0, b1);
                mma16816(c[0][nj * 2 + 1], a0[0], a0[1], a0[2], a0[3], b2, b3);
                mma16816(c[1][nj * 2],     a1[0], a1[1], a1[2], a1[3], b0, b1);
                mma16816(c[1][nj * 2 + 1], a1[0], a1[1], a1[2], a1[3], b2, b3);
            }
        }
        if (s + 2 < steps) {
            gemm_fill(sbase, ((s + 2) % 3) * GBUF, s + 2, tid, pix0, out0, Pa, K, A, W);
            asm volatile("cp.async.commit_group;\n");
        }
    }

    const int qid = lane >> 2, rid = lane & 3;
#pragma unroll
    for (int mi = 0; mi < 2; mi++) {
        const int pr = pix0 + wm + mi * 16 + qid;
#pragma unroll
        for (int ni = 0; ni < 8; ni++) {
            const int o = out0 + wn + ni * 8 + rid * 2;
            const float2 bb = *reinterpret_cast<const float2*>(bias + o);
            St<OutT>::s(Out + (size_t)pr * Po + o,
                        fmaxf(c[mi][ni][0] + bb.x, 0.f), fmaxf(c[mi][ni][1] + bb.y, 0.f));
            St<OutT>::s(Out + (size_t)(pr + 8) * Po + o,
                        fmaxf(c[mi][ni][2] + bb.x, 0.f), fmaxf(c[mi][ni][3] + bb.y, 0.f));
        }
    }
}

// ---------------- fused q2 GEMM + attention ----------------
// Computes q = relu(bn(Wq2 * t1)) for a 128-pixel tile (K=256), keeps q in smem
// (fp16), then runs the 19-key softmax attention and writes ctx directly.
#define QPITCH 264   // halfs per qs row (528B, 16B-aligned, conflict-staggered)

__global__ __launch_bounds__(512, 1) void gemm_q2_attn(
    const __half* __restrict__ A,     // t1 [pix][256]
    const __half* __restrict__ W,     // Wq2 [256][256]
    const float*  __restrict__ bias,  // bq2
    const float*  __restrict__ kf,
    const float*  __restrict__ vf,
    __half*       __restrict__ ctx)   // [pix][256]
{
    extern __shared__ char smemg[];
    const uint32_t sbase = (uint32_t)__cvta_generic_to_shared(smemg);
    float* ks = reinterpret_cast<float*>(smemg + SMEM_GEMM);
    float* vs = ks + 256 * 19;
    const int tid  = threadIdx.x;
    const int warp = tid >> 5, lane = tid & 31;
    const int wm   = (warp >> 2) * 32;
    const int wn   = (warp & 3) * 64;
    const int pix0 = blockIdx.x * 128;
    const int bo   = (pix0 / HWC) * 256 * 19;

    // load k/v into dedicated smem region (ordered by the epilogue barrier)
    for (int i = tid; i < 256 * 19; i += 512) {
        ks[i] = kf[bo + i];
        vs[i] = vf[bo + i];
    }

    float c[2][8][4];
#pragma unroll
    for (int i = 0; i < 2; i++)
#pragma unroll
        for (int j = 0; j < 8; j++)
#pragma unroll
            for (int r = 0; r < 4; r++) c[i][j][r] = 0.f;

    gemm_fill(sbase, 0, 0, tid, pix0, 0, 256, 256, A, W);
    asm volatile("cp.async.commit_group;\n");
    gemm_fill(sbase, GBUF, 1, tid, pix0, 0, 256, 256, A, W);
    asm volatile("cp.async.commit_group;\n");

    for (int s = 0; s < 8; s++) {
        if (s < 7) asm volatile("cp.async.wait_group 1;\n");
        else       asm volatile("cp.async.wait_group 0;\n");
        __syncthreads();

        const uint32_t aB = sbase + (s % 3) * GBUF;
        const uint32_t bB = aB + GA_BYTES;
        const uint32_t aRow = aB + (wm + (lane & 15)) * APITCHB + (lane >> 4) * 16;
#pragma unroll
        for (int kss = 0; kss < 2; kss++) {
            const int kb2 = kss * 32;
            uint32_t a0[4], a1[4];
            LDSM4(a0[0], a0[1], a0[2], a0[3], aRow + kb2);
            LDSM4(a1[0], a1[1], a1[2], a1[3], aRow + 16 * APITCHB + kb2);
#pragma unroll
            for (int nj = 0; nj < 4; nj++) {
                const int row = wn + nj * 16 + (lane & 7) + ((lane >> 4) & 1) * 8;
                const uint32_t addr = bB + row * APITCHB + kb2 + ((lane >> 3) & 1) * 16;
                uint32_t b0, b1, b2, b3;
                LDSM4(b0, b1, b2, b3, addr);
                mma16816(c[0][nj * 2],     a0[0], a0[1], a0[2], a0[3], b0, b1);
                mma16816(c[0][nj * 2 + 1], a0[0], a0[1], a0[2], a0[3], b2, b3);
                mma16816(c[1][nj * 2],     a1[0], a1[1], a1[2], a1[3], b0, b1);
                mma16816(c[1][nj * 2 + 1], a1[0], a1[1], a1[2], a1[3], b2, b3);
            }
        }
        if (s + 2 < 8) {
            gemm_fill(sbase, ((s + 2) % 3) * GBUF, s + 2, tid, pix0, 0, 256, 256, A, W);
            asm volatile("cp.async.commit_group;\n");
        }
    }

    // all LDSM reads of the pipeline buffers done -> safe to reuse as q store
    __syncthreads();
    __half* qs = reinterpret_cast<__half*>(smemg);
    const int qid = lane >> 2, rid = lane & 3;
#pragma unroll
    for (int mi = 0; mi < 2; mi++) {
        const int pr = wm + mi * 16 + qid;
#pragma unroll
        for (int ni = 0; ni < 8; ni++) {
            const int o = wn + ni * 8 + rid * 2;
            const float2 bb = *reinterpret_cast<const float2*>(bias + o);
            *reinterpret_cast<__half2*>(qs + pr * QPITCH + o) =
                __floats2half2_rn(fmaxf(c[mi][ni][0] + bb.x, 0.f),
                                  fmaxf(c[mi][ni][1] + bb.y, 0.f));
            *reinterpret_cast<__half2*>(qs + (pr + 8) * QPITCH + o) =
                __floats2half2_rn(fmaxf(c[mi][ni][2] + bb.x, 0.f),
                                  fmaxf(c[mi][ni][3] + bb.y, 0.f));
        }
    }
    __syncthreads();

    // attention: 16 warps x 8 pixels
#pragma unroll 1
    for (int p = 0; p < 8; p++) {
        const int pl = warp * 8 + p;
        float qv[8];
#pragma unroll
        for (int i = 0; i < 8; i++)
            qv[i] = __half2float(qs[pl * QPITCH + lane + 32 * i]);

        float sim[19];
#pragma unroll
        for (int j = 0; j < 19; j++) {
            float s = 0.f;
#pragma unroll
            for (int i = 0; i < 8; i++) s += qv[i] * ks[(lane + 32 * i) * 19 + j];
#pragma unroll
            for (int o = 16; o > 0; o >>= 1) s += __shfl_xor_sync(0xffffffffu, s, o);
            sim[j] = s * 0.0625f;
        }
        float mx = sim[0];
#pragma unroll
        for (int j = 1; j < 19; j++) mx = fmaxf(mx, sim[j]);
        float den = 0.f;
#pragma unroll
        for (int j = 0; j < 19; j++) { sim[j] = __expf(sim[j] - mx); den += sim[j]; }
        const float inv = 1.f / den;

        __half* cp = ctx + (size_t)(pix0 + pl) * 256;
#pragma unroll
        for (int i = 0; i < 8; i++) {
            const int ch = lane + 32 * i;
            float acc = 0.f;
#pragma unroll
            for (int j = 0; j < 19; j++) acc += sim[j] * vs[ch * 19 + j];
            cp[ch] = __float2half(acc * inv);
        }
    }
}

// ---------------- conv3x3: NHWC, 3-stage cp.async, tap reuse (R4 proven) ----------------
__device__ __forceinline__ void conv_stage(
    uint32_t sbase, char* smemc, int bufo, int s,
    int tid, int b, int y0, int m0,
    const __half* __restrict__ Wre2, const __half* __restrict__ nhwc)
{
    const int dy = s >> 5;
    const int kc = (s & 31) << 5;
    {
        const int m = tid >> 2, part = tid & 3;
#pragma unroll
        for (int t = 0; t < 3; t++) {
            const __half* g = Wre2 + (((size_t)((dy * 3 + t) * 512 + m0 + m)) << 10)
                              + kc + part * 8;
            uint32_t d = sbase + bufo + (t * 128 + m) * APITCHB + part * 16;
            CP16(d, g);
        }
    }
    {
        const int yy = y0 + dy - 1;
        const bool yok = (unsigned)yy < (unsigned)H_IMG;
        const __half* rowbase = nhwc + (((size_t)(b * H_IMG + yy) * W_IMG) << 10) + kc;
#pragma unroll
        for (int i = 0; i < 3; i++) {
            int j = tid + i * 512;
            if (j < BROWS * 4) {
                int n = j >> 2, p = j & 3;
                uint32_t doff = (uint32_t)bufo + ABYTES + n * APITCHB + p * 16;
                int xx = n - 1;
                if (yok && (unsigned)xx < (unsigned)W_IMG) {
                    CP16(sbase + doff, rowbase + ((size_t)xx << 10) + p * 8);
                } else {
                    *reinterpret_cast<uint4*>(smemc + doff) = make_uint4(0, 0, 0, 0);
                }
            }
        }
    }
}

__global__ __launch_bounds__(512, 1) void conv3_tc(
    const __half* __restrict__ Wre2,
    const __half* __restrict__ nhwc,
    const float*  __restrict__ bias,
    float*        __restrict__ Out)
{
    extern __shared__ char smemc[];
    const uint32_t sbase = (uint32_t)__cvta_generic_to_shared(smemc);
    const int tid  = threadIdx.x;
    const int warp = tid >> 5, lane = tid & 31;
    const int wm   = (warp >> 2) * 32;
    const int wn   = (warp & 3) * 64;
    const int m0   = blockIdx.y * 128;
    const int b    = blockIdx.x >> 7;
    const int y0   = blockIdx.x & 127;

    float c[2][8][4];
#pragma unroll
    for (int i = 0; i < 2; i++)
#pragma unroll
        for (int j = 0; j < 8; j++)
#pragma unroll
            for (int r = 0; r < 4; r++) c[i][j][r] = 0.f;

    conv_stage(sbase, smemc, 0, 0, tid, b, y0, m0, Wre2, nhwc);
    asm volatile("cp.async.commit_group;\n");
    conv_stage(sbase, smemc, BUFB, 1, tid, b, y0, m0, Wre2, nhwc);
    asm volatile("cp.async.commit_group;\n");

    for (int s = 0; s < 96; s++) {
        if (s < 95) asm volatile("cp.async.wait_group 1;\n");
        else        asm volatile("cp.async.wait_group 0;\n");
        __syncthreads();

        const uint32_t aB = sbase + (s % 3) * BUFB;
        const uint32_t bB = aB + ABYTES;
#pragma unroll
        for (int dx = 0; dx < 3; dx++) {
            const uint32_t aRow = aB + (dx * 128 + wm + (lane & 15)) * APITCHB
                                  + (lane >> 4) * 16;
#pragma unroll
            for (int ks = 0; ks < 2; ks++) {
                const int kb2 = ks * 32;
                uint32_t a0[4], a1[4];
                LDSM4(a0[0], a0[1], a0[2], a0[3], aRow + kb2);
                LDSM4(a1[0], a1[1], a1[2], a1[3], aRow + 16 * APITCHB + kb2);
#pragma unroll
                for (int nj = 0; nj < 4; nj++) {
                    const int row = wn + nj * 16 + dx + (lane & 7) + ((lane >> 4) & 1) * 8;
                    const uint32_t addr = bB + row * APITCHB + kb2 + ((lane >> 3) & 1) * 16;
                    uint32_t b0, b1, b2, b3;
                    LDSM4(b0, b1, b2, b3, addr);
                    mma16816(c[0][nj * 2],     a0[0], a0[1], a0[2], a0[3], b0, b1);
                    mma16816(c[0][nj * 2 + 1], a0[0], a0[1], a0[2], a0[3], b2, b3);
                    mma16816(c[1][nj * 2],     a1[0], a1[1], a1[2], a1[3], b0, b1);
                    mma16816(c[1][nj * 2 + 1], a1[0], a1[1], a1[2], a1[3], b2, b3);
                }
            }
        }
        if (s + 2 < 96) {
            conv_stage(sbase, smemc, ((s + 2) % 3) * BUFB, s + 2, tid, b, y0, m0, Wre2, nhwc);
            asm volatile("cp.async.commit_group;\n");
        }
    }

    const int qid = lane >> 2, rid = lane & 3;
    float* outB = Out + ((size_t)b * 512) * HWC + (size_t)y0 * W_IMG;
#pragma unroll
    for (int mi = 0; mi < 2; mi++) {
        const int mr = wm + mi * 16 + qid;
        const float bs0 = bias[m0 + mr], bs1 = bias[m0 + mr + 8];
#pragma unroll
        for (int ni = 0; ni < 8; ni++) {
            const int px = wn + ni * 8 + rid * 2;
            *reinterpret_cast<float2*>(outB + (size_t)(m0 + mr) * HWC + px) =
                make_float2(fmaxf(c[mi][ni][0] + bs0, 0.f),
                            fmaxf(c[mi][ni][1] + bs0, 0.f));
            *reinterpret_cast<float2*>(outB + (size_t)(m0 + mr + 8) * HWC + px) =
                make_float2(fmaxf(c[mi][ni][2] + bs1, 0.f),
                            fmaxf(c[mi][ni][3] + bs1, 0.f));
        }
    }
}

// ---------------- launcher ----------------
extern "C" void kernel_launch(void* const* d_in, const int* in_sizes, int n_in,
                              void* d_out, int out_size)
{
    const float *x, *proxy, *wq1, *wq2, *wk1, *wk2, *wv, *wout, *wbot;
    const float *bnq1, *bnq2, *bnk1, *bnk2, *bnv, *bnout, *bnbot;

    if (n_in >= 16 && in_sizes[3] == 1024) {
        x     = (const float*)d_in[0];  proxy = (const float*)d_in[1];
        wq1   = (const float*)d_in[2];  bnq1  = (const float*)d_in[3];
        wq2   = (const float*)d_in[4];  bnq2  = (const float*)d_in[5];
        wk1   = (const float*)d_in[6];  bnk1  = (const float*)d_in[7];
        wk2   = (const float*)d_in[8];  bnk2  = (const float*)d_in[9];
        wv    = (const float*)d_in[10]; bnv   = (const float*)d_in[11];
        wout  = (const float*)d_in[12]; bnout = (const float*)d_in[13];
        wbot  = (const float*)d_in[14]; bnbot = (const float*)d_in[15];
    } else {
        x     = (const float*)d_in[0];  proxy = (const float*)d_in[1];
        wq1   = (const float*)d_in[2];  wq2   = (const float*)d_in[3];
        wk1   = (const float*)d_in[4];  wk2   = (const float*)d_in[5];
        wv    = (const float*)d_in[6];  wout  = (const float*)d_in[7];
        wbot  = (const float*)d_in[8];
        bnq1  = (const float*)d_in[9];  bnq2  = (const float*)d_in[10];
        bnk1  = (const float*)d_in[11]; bnk2  = (const float*)d_in[12];
        bnv   = (const float*)d_in[13]; bnout = (const float*)d_in[14];
        bnbot = (const float*)d_in[15];
    }

    __half *cat, *t1, *ctx, *Wq1h, *Wq2h, *Wouth, *Wre;
    float *bq1, *bq2, *bout, *bbot, *tk1, *kf, *vf;
    cudaGetSymbolAddress((void**)&cat,   g_cat);
    cudaGetSymbolAddress((void**)&t1,    g_t1);
    cudaGetSymbolAddress((void**)&ctx,   g_ctx);
    cudaGetSymbolAddress((void**)&Wq1h,  g_Wq1);
    cudaGetSymbolAddress((void**)&Wq2h,  g_Wq2);
    cudaGetSymbolAddress((void**)&Wouth, g_Wout);
    cudaGetSymbolAddress((void**)&Wre,   g_Wre);
    cudaGetSymbolAddress((void**)&bq1,   g_bq1);
    cudaGetSymbolAddress((void**)&bq2,   g_bq2);
    cudaGetSymbolAddress((void**)&bout,  g_bout);
    cudaGetSymbolAddress((void**)&bbot,  g_bbot);
    cudaGetSymbolAddress((void**)&tk1,   g_tk1);
    cudaGetSymbolAddress((void**)&kf,    g_kf);
    cudaGetSymbolAddress((void**)&vf,    g_vf);

    cudaFuncSetAttribute(conv3_tc, cudaFuncAttributeMaxDynamicSharedMemorySize, SMEM_CONV);
    cudaFuncSetAttribute(gemm_nhwc<__half>, cudaFuncAttributeMaxDynamicSharedMemorySize, SMEM_GEMM);
    cudaFuncSetAttribute(gemm_q2_attn, cudaFuncAttributeMaxDynamicSharedMemorySize, SMEM_FUSED);

    // --- prep ---
    x_to_cat<<<dim3(HWC / 64, 8, 2), 256>>>(x, cat);
    fold_w_kernel<<<(256 * 512 + 255) / 256, 256>>>(wq1, bnq1, Wq1h, bq1, 256, 512);
    fold_w_kernel<<<(256 * 256 + 255) / 256, 256>>>(wq2, bnq2, Wq2h, bq2, 256, 256);
    fold_w_kernel<<<(512 * 256 + 255) / 256, 256>>>(wout, bnout, Wouth, bout, 512, 256);
    fold_wbot_kernel<<<(9 * 1024 * 512 + 255) / 256, 256>>>(wbot, bnbot, Wre, bbot);

    // --- tiny k/v path ---
    kv_stage_kernel<<<(2 * 256 * 19 + 255) / 256, 256>>>(wk1, bnk1, proxy, tk1, 256, 512);
    kv_stage_kernel<<<(2 * 256 * 19 + 255) / 256, 256>>>(wv,  bnv,  proxy, vf,  256, 512);
    kv_stage_kernel<<<(2 * 256 * 19 + 255) / 256, 256>>>(wk2, bnk2, tk1, kf, 256, 256);

    // --- q path: q1 GEMM, then fused q2 GEMM + attention -> ctx ---
    gemm_nhwc<__half><<<dim3(NPIX / 128, 1), 512, SMEM_GEMM>>>(
        cat + 512, 1024, Wq1h, bq1, t1, 256, 512);
    gemm_q2_attn<<<dim3(NPIX / 128, 1), 512, SMEM_FUSED>>>(
        t1, Wq2h, bq2, kf, vf, ctx);

    // --- wout GEMM -> cat[pix][0:512] ---
    gemm_nhwc<__half><<<dim3(NPIX / 128, 2), 512, SMEM_GEMM>>>(
        ctx, 256, Wouth, bout, cat, 1024, 256);

    // --- bottleneck conv3x3 ---
    conv3_tc<<<dim3(2 * H_IMG, 4), 512, SMEM_CONV>>>(Wre, cat, bbot, (float*)d_out);
}